// round 13
// baseline (speedup 1.0000x reference)
#include <cuda_runtime.h>
#include <cuda_bf16.h>
#include <cuda_fp16.h>
#include <math.h>
#include <stdint.h>

// Problem dims
constexpr int NB = 120;
constexpr int NT = 20;
constexpr int NL = 144;
constexpr int ND = 64;
constexpr int NH = 1024;
constexpr int NA = 256;
constexpr int NR = NL * ND;     // 9216
constexpr int NG = 4 * NH;      // 4096
constexpr int NK = NR + NH;     // 10240 (concat v|h)

// Recurrent GEMM config (fp16 2-pass)
constexpr int KSPLIT = 8;
constexpr int KPER = NK / KSPLIT;   // 1280
constexpr int BK = 16;
constexpr int NIT = KPER / BK;      // 80
constexpr int SSTR = 24;            // padded smem row stride (fp16 elems)
constexpr int STG_ELEMS = 3 * (128 * SSTR);   // A(1) + W(2) = 9216 els
constexpr int NSTG = 4;
constexpr int SMEM_BYTES = NSTG * STG_ELEMS * 2; // 73728 B

// XA GEMM config (unchanged bf16 3-pass)
constexpr int XA_SSTR = 72;
constexpr int XA_SMEM = (2 * 128 * XA_SSTR + 2 * 256 * XA_SSTR) * 2; // 110592 B

// -------- scratch (device globals; no runtime allocation) --------
__device__ float g_XA[(size_t)NB * NT * NL * NA]; // 354 MB: feature @ Wxa
__device__ float g_h0[NB * NH];
__device__ float g_c[NB * NH];
__device__ float g_f0[NB * ND];
__device__ float g_gp[KSPLIT][NB * NG];   // per-K-split GEMM partials
// fp16 operands for recurrent GEMM (.bss zero-init keeps pad rows zero)
__device__ __align__(16) __half g_Af[128 * NK];            // A single fp16
__device__ __align__(16) __half g_W16h[(size_t)NG * NK];   // W fp16 hi
__device__ __align__(16) __half g_W16l[(size_t)NG * NK];   // W fp16 lo
// bf16 hi/lo for XA prologue
__device__ __align__(16) __nv_bfloat16 g_WxaThi[NA * ND]; // Wxa^T [256][64]
__device__ __align__(16) __nv_bfloat16 g_WxaTlo[NA * ND];

__device__ __forceinline__ float sigmoidf_(float x) {
    return 1.f / (1.f + expf(-x));
}

__device__ __forceinline__ void split_bf16(float x, __nv_bfloat16& hi, __nv_bfloat16& lo) {
    hi = __float2bfloat16(x);
    lo = __float2bfloat16(x - __bfloat162float(hi));
}

__device__ __forceinline__ void split_half(float x, __half& hi, __half& lo) {
    hi = __float2half_rn(x);
    lo = __float2half_rn(x - __half2float(hi));
}

__device__ __forceinline__ void cp_async16(void* smem_dst, const void* gmem_src) {
    unsigned sa = (unsigned)__cvta_generic_to_shared(smem_dst);
    asm volatile("cp.async.cg.shared.global [%0], [%1], 16;\n" :: "r"(sa), "l"(gmem_src));
}

__device__ __forceinline__ void ldsm_x4_b(unsigned* r, const __nv_bfloat16* p) {
    unsigned sa = (unsigned)__cvta_generic_to_shared(p);
    asm volatile("ldmatrix.sync.aligned.m8n8.x4.shared.b16 {%0,%1,%2,%3}, [%4];"
                 : "=r"(r[0]), "=r"(r[1]), "=r"(r[2]), "=r"(r[3]) : "r"(sa));
}

__device__ __forceinline__ void ldsm_x4_h(unsigned* r, const __half* p) {
    unsigned sa = (unsigned)__cvta_generic_to_shared(p);
    asm volatile("ldmatrix.sync.aligned.m8n8.x4.shared.b16 {%0,%1,%2,%3}, [%4];"
                 : "=r"(r[0]), "=r"(r[1]), "=r"(r[2]), "=r"(r[3]) : "r"(sa));
}

#define MMA_BF16(C, AV, B0, B1) \
    asm volatile( \
        "mma.sync.aligned.m16n8k16.row.col.f32.bf16.bf16.f32 " \
        "{%0,%1,%2,%3}, {%4,%5,%6,%7}, {%8,%9}, {%0,%1,%2,%3};\n" \
        : "+f"((C)[0]), "+f"((C)[1]), "+f"((C)[2]), "+f"((C)[3]) \
        : "r"((AV)[0]), "r"((AV)[1]), "r"((AV)[2]), "r"((AV)[3]), \
          "r"(B0), "r"(B1))

#define MMA_F16(C, AV, B0, B1) \
    asm volatile( \
        "mma.sync.aligned.m16n8k16.row.col.f32.f16.f16.f32 " \
        "{%0,%1,%2,%3}, {%4,%5,%6,%7}, {%8,%9}, {%0,%1,%2,%3};\n" \
        : "+f"((C)[0]), "+f"((C)[1]), "+f"((C)[2]), "+f"((C)[3]) \
        : "r"((AV)[0]), "r"((AV)[1]), "r"((AV)[2]), "r"((AV)[3]), \
          "r"(B0), "r"(B1))

// ---------------- init: f0 = mean_l feature[b*T+0, l, :] ----------------
__global__ void k_f0(const float* __restrict__ feat) {
    int b = blockIdx.x, d = threadIdx.x; // 64 threads
    const float* p = feat + (size_t)b * NT * NL * ND;
    float s = 0.f;
    for (int l = 0; l < NL; l++) s += p[l * ND + d];
    g_f0[b * ND + d] = s * (1.f / NL);
}

// h0 = tanh(f0 @ Wh_w^T + Wh_b), c0 = tanh(f0 @ Wc_w^T + Wc_b)
__global__ void k_h0c0(const float* __restrict__ Wh_w, const float* __restrict__ Wh_b,
                       const float* __restrict__ Wc_w, const float* __restrict__ Wc_b) {
    __shared__ float fs[ND];
    int b = blockIdx.x;
    int j = blockIdx.y * 128 + threadIdx.x;
    if (threadIdx.x < ND) fs[threadIdx.x] = g_f0[b * ND + threadIdx.x];
    __syncthreads();
    float sh = Wh_b[j], sc = Wc_b[j];
    #pragma unroll 8
    for (int d = 0; d < ND; d++) {
        float x = fs[d];
        sh += x * Wh_w[j * ND + d];
        sc += x * Wc_w[j * ND + d];
    }
    float h = tanhf(sh);
    g_h0[b * NH + j] = h;
    g_c[b * NH + j] = tanhf(sc);
    g_Af[b * NK + NR + j] = __float2half_rn(h);
}

// split W = [W_ih | W_hh] into fp16 hi/lo   [NG][NK]
__global__ void k_wsplit(const float* __restrict__ W_ih, const float* __restrict__ W_hh) {
    size_t idx = (size_t)blockIdx.x * 256 + threadIdx.x; // NG*NK exactly
    int n = (int)(idx / NK), k = (int)(idx % NK);
    float x = (k < NR) ? W_ih[(size_t)n * NR + k] : W_hh[(size_t)n * NH + (k - NR)];
    __half hi, lo;
    split_half(x, hi, lo);
    g_W16h[idx] = hi;
    g_W16l[idx] = lo;
}

// transpose + split Wxa [64][256] -> WxaT [256][64]
__global__ void k_wxat(const float* __restrict__ Wxa) {
    int d = blockIdx.x, a = threadIdx.x; // 64 blocks x 256 threads
    __nv_bfloat16 hi, lo;
    split_bf16(Wxa[d * NA + a], hi, lo);
    g_WxaThi[a * ND + d] = hi;
    g_WxaTlo[a * ND + d] = lo;
}

// ---------------- XA = feature @ Wxa via tensor cores (bf16 3-pass HMMA) ----------------
__global__ void __launch_bounds__(512) k_xa2(const float* __restrict__ feat) {
    extern __shared__ __nv_bfloat16 xsm[];
    __nv_bfloat16* sA = xsm;                       // 2 arr x 128 x XA_SSTR
    __nv_bfloat16* sW = xsm + 2 * 128 * XA_SSTR;   // 2 arr x 256 x XA_SSTR

    const int tid = threadIdx.x;
    const int wid = tid >> 5, lane = tid & 31;
    const int m0 = blockIdx.x * 128;

    #pragma unroll
    for (int q = 0; q < 8; q++) {
        int c = tid + q * 512;
        int kc = c & 7, row = (c >> 3) & 255, arr = c >> 11;
        const __nv_bfloat16* src = (arr ? g_WxaTlo : g_WxaThi) + row * ND + kc * 8;
        cp_async16(sW + arr * (256 * XA_SSTR) + row * XA_SSTR + kc * 8, src);
    }
    asm volatile("cp.async.commit_group;\n");

    #pragma unroll
    for (int q = 0; q < 4; q++) {
        int i = tid + q * 512;
        int row = i >> 4, c4 = (i & 15) * 4;
        float4 f = *reinterpret_cast<const float4*>(feat + (size_t)(m0 + row) * ND + c4);
        __nv_bfloat16 h0, l0, h1, l1, h2, l2, h3, l3;
        split_bf16(f.x, h0, l0); split_bf16(f.y, h1, l1);
        split_bf16(f.z, h2, l2); split_bf16(f.w, h3, l3);
        __nv_bfloat162* ph = reinterpret_cast<__nv_bfloat162*>(sA + row * XA_SSTR + c4);
        __nv_bfloat162* pl = reinterpret_cast<__nv_bfloat162*>(sA + 128 * XA_SSTR + row * XA_SSTR + c4);
        ph[0] = __nv_bfloat162(h0, h1); ph[1] = __nv_bfloat162(h2, h3);
        pl[0] = __nv_bfloat162(l0, l1); pl[1] = __nv_bfloat162(l2, l3);
    }
    asm volatile("cp.async.wait_group 0;\n");
    __syncthreads();

    const int warp_m = (wid & 3) * 32;
    const int warp_n = (wid >> 2) * 64;
    const int a_row_l = lane & 15;
    const int a_col_l = (lane >> 4) * 8;
    const int b_row_l = (lane & 7) + ((lane >> 4) << 3);
    const int b_col_l = ((lane >> 3) & 1) * 8;

    float acc[2][8][4];
    #pragma unroll
    for (int mi = 0; mi < 2; mi++)
        #pragma unroll
        for (int nt = 0; nt < 8; nt++)
            #pragma unroll
            for (int c = 0; c < 4; c++) acc[mi][nt][c] = 0.f;

    #pragma unroll
    for (int ks = 0; ks < 4; ks++) {
        unsigned af[2][2][4];
        #pragma unroll
        for (int arr = 0; arr < 2; arr++)
            #pragma unroll
            for (int mi = 0; mi < 2; mi++)
                ldsm_x4_b(af[arr][mi],
                          sA + arr * (128 * XA_SSTR) +
                          (warp_m + mi * 16 + a_row_l) * XA_SSTR + ks * 16 + a_col_l);
        #pragma unroll
        for (int nj = 0; nj < 4; nj++) {
            unsigned bh[4], bl[4];
            ldsm_x4_b(bh, sW + (warp_n + nj * 16 + b_row_l) * XA_SSTR + ks * 16 + b_col_l);
            ldsm_x4_b(bl, sW + 256 * XA_SSTR + (warp_n + nj * 16 + b_row_l) * XA_SSTR + ks * 16 + b_col_l);
            #pragma unroll
            for (int mi = 0; mi < 2; mi++) {
                #pragma unroll
                for (int p = 0; p < 2; p++) {
                    float* c = acc[mi][nj * 2 + p];
                    MMA_BF16(c, af[0][mi], bh[p * 2], bh[p * 2 + 1]);
                    MMA_BF16(c, af[0][mi], bl[p * 2], bl[p * 2 + 1]);
                    MMA_BF16(c, af[1][mi], bh[p * 2], bh[p * 2 + 1]);
                }
            }
        }
    }

    const int g = lane >> 2, q2 = (lane & 3) * 2;
    #pragma unroll
    for (int mi = 0; mi < 2; mi++) {
        #pragma unroll
        for (int nt = 0; nt < 8; nt++) {
            int col = warp_n + nt * 8 + q2;
            int r0 = warp_m + mi * 16 + g;
            *reinterpret_cast<float2*>(&g_XA[(size_t)(m0 + r0) * NA + col]) =
                make_float2(acc[mi][nt][0], acc[mi][nt][1]);
            *reinterpret_cast<float2*>(&g_XA[(size_t)(m0 + r0 + 8) * NA + col]) =
                make_float2(acc[mi][nt][2], acc[mi][nt][3]);
        }
    }
}

// ---------------- fused per-step kernel: LSTM(t-1) + attention + v ----------------
__global__ void __launch_bounds__(1024) k_step(const float* __restrict__ Wha,
                                               const float* __restrict__ Wb,
                                               const float* __restrict__ bb,
                                               const float* __restrict__ wa,
                                               const float* __restrict__ b_ih,
                                               const float* __restrict__ b_hh,
                                               const float* __restrict__ feat,
                                               float* __restrict__ out_vis,
                                               float* __restrict__ out_alp,
                                               float* __restrict__ out_bet,
                                               float* __restrict__ out_hdd,
                                               int t) {
    __shared__ float hs[NH];
    __shared__ float pa[4][NA];
    __shared__ float pb[8][ND];
    __shared__ float ha_s[NA];
    __shared__ float wa_s[NA];
    __shared__ float e_s[NL];
    __shared__ float red[256];
    __shared__ float alpha_s[NL];
    __shared__ float beta_s[ND];
    const int b = blockIdx.x, tid = threadIdx.x;

    if (t > 0) {
        const int j = tid;
        float gi = b_ih[j] + b_hh[j];
        float gf = b_ih[NH + j] + b_hh[NH + j];
        float gg = b_ih[2 * NH + j] + b_hh[2 * NH + j];
        float go = b_ih[3 * NH + j] + b_hh[3 * NH + j];
        #pragma unroll
        for (int z = 0; z < KSPLIT; z++) {
            const float* gp = g_gp[z] + (size_t)b * NG;
            gi += gp[j];
            gf += gp[NH + j];
            gg += gp[2 * NH + j];
            go += gp[3 * NH + j];
        }
        float c = sigmoidf_(gf) * g_c[b * NH + j] + sigmoidf_(gi) * tanhf(gg);
        float h = sigmoidf_(go) * tanhf(c);
        g_c[b * NH + j] = c;
        hs[j] = h;
        out_hdd[(size_t)(b * NT + (t - 1)) * NH + j] = h;
        g_Af[b * NK + NR + j] = __float2half_rn(h);
    } else {
        hs[tid] = g_h0[b * NH + tid];
    }
    if (tid < NA) wa_s[tid] = wa[tid];
    __syncthreads();

    {
        int a = tid & 255, q = tid >> 8;
        int k0 = q * 256;
        float s = 0.f;
        #pragma unroll 16
        for (int k = 0; k < 256; k++) s += hs[k0 + k] * Wha[(size_t)(k0 + k) * NA + a];
        pa[q][a] = s;
    }
    if (tid < 512) {
        int d = tid & 63, q = tid >> 6;
        int k0 = q * 128;
        float s = 0.f;
        #pragma unroll 16
        for (int k = 0; k < 128; k++) s += hs[k0 + k] * Wb[(size_t)(k0 + k) * ND + d];
        pb[q][d] = s;
    }
    __syncthreads();
    if (tid < 256) {
        ha_s[tid] = pa[0][tid] + pa[1][tid] + pa[2][tid] + pa[3][tid];
    } else if (tid < 320) {
        int d = tid - 256;
        float tot = bb[d];
        #pragma unroll
        for (int i = 0; i < 8; i++) tot += pb[i][d];
        float bt = sigmoidf_(tot);
        beta_s[d] = bt;
        out_bet[(size_t)(b * NT + t) * ND + d] = bt;
    }
    __syncthreads();

    {
        const int w = tid >> 5, lane = tid & 31;
        const float* XAb = g_XA + (size_t)((b * NT + t) * NL) * NA;
        for (int l = w; l < NL; l += 32) {
            float s = 0.f;
            #pragma unroll
            for (int i = 0; i < 8; i++) {
                int a = lane + i * 32;
                s += tanhf(XAb[(size_t)l * NA + a] + ha_s[a]) * wa_s[a];
            }
            #pragma unroll
            for (int o = 16; o > 0; o >>= 1) s += __shfl_xor_sync(0xffffffffu, s, o);
            if (lane == 0) e_s[l] = s;
        }
    }
    __syncthreads();

    float v = -1e30f;
    if (tid < NL) v = e_s[tid];
    if (tid < 256) red[tid] = v;
    __syncthreads();
    for (int s2 = 128; s2 > 0; s2 >>= 1) {
        if (tid < s2) red[tid] = fmaxf(red[tid], red[tid + s2]);
        __syncthreads();
    }
    float mx = red[0];
    __syncthreads();
    float ex = (tid < NL) ? expf(v - mx) : 0.f;
    if (tid < 256) red[tid] = ex;
    __syncthreads();
    for (int s2 = 128; s2 > 0; s2 >>= 1) {
        if (tid < s2) red[tid] += red[tid + s2];
        __syncthreads();
    }
    float denom = red[0];
    if (tid < NL) {
        float al = ex / denom;
        alpha_s[tid] = al;
        out_alp[(size_t)(b * NT + t) * NL + tid] = al;
    }
    __syncthreads();

    {
        const float* fb = feat + (size_t)(b * NT + t) * NR;
        float* ob = out_vis + (size_t)(b * NT + t) * NR;
        __half* af = g_Af + (size_t)b * NK;
        #pragma unroll
        for (int q = 0; q < NR / 1024; q++) {
            int r = tid + q * 1024;
            int l = r >> 6, d = r & 63;
            float val = fb[r] * (1.f + alpha_s[l]) * beta_s[d];
            ob[r] = val;
            af[r] = __float2half_rn(val);
        }
    }
}

// ---------------- HMMA GEMM: gp[z] = A[128,Kz] @ W[4096,Kz]^T ----------------
// fp16 2-pass: acc = A*Whi + A*Wlo. BM=128, BN=128, BK=16, 8 warps,
// ldmatrix.x4, 4-stage cp.async, ONE sync per iter, 2 CTAs/SM.
__global__ void __launch_bounds__(256, 2) k_mma() {
    extern __shared__ __half smem[];

    const int tid = threadIdx.x;
    const int wid = tid >> 5, lane = tid & 31;
    const int warp_m = (wid & 3) * 32;
    const int warp_n = (wid >> 2) * 64;
    const int n0 = blockIdx.x * 128;
    const int z = blockIdx.y;
    const int kbase = z * KPER;

    // per iter: A 256 chunks + W 512 chunks of 16B; 3 per thread.
    auto issue = [&](int stage, int kt) {
        const int k0 = kbase + kt * BK;
        __half* sA = smem + stage * STG_ELEMS;
        __half* sW = sA + 128 * SSTR;
        {
            // A: 256 chunks: kc = tid&1, row = tid>>1
            int kc = tid & 1, row = tid >> 1;
            const __half* srcA = g_Af + (size_t)row * NK + k0 + kc * 8;
            cp_async16(sA + row * SSTR + kc * 8, srcA);
            // W: 512 chunks: c = tid + q*256; kc=c&1, arr=(c>>1)&1, row=c>>2 (+64 for q=1)
            #pragma unroll
            for (int q = 0; q < 2; q++) {
                int c = tid + q * 256;
                int wkc = c & 1, arr = (c >> 1) & 1, row2 = c >> 2;
                const __half* srcW = (arr ? g_W16l : g_W16h) + (size_t)(n0 + row2) * NK + k0 + wkc * 8;
                cp_async16(sW + arr * (128 * SSTR) + row2 * SSTR + wkc * 8, srcW);
            }
        }
        asm volatile("cp.async.commit_group;\n");
    };

    float acc[2][8][4];
    #pragma unroll
    for (int mi = 0; mi < 2; mi++)
        #pragma unroll
        for (int nt = 0; nt < 8; nt++)
            #pragma unroll
            for (int c = 0; c < 4; c++) acc[mi][nt][c] = 0.f;

    issue(0, 0);
    issue(1, 1);

    const int a_row_l = lane & 15;
    const int a_col_l = (lane >> 4) * 8;
    const int b_row_l = (lane & 7) + ((lane >> 4) << 3);
    const int b_col_l = ((lane >> 3) & 1) * 8;

    for (int kt = 0; kt < NIT; kt++) {
        if (kt + 2 < NIT) {
            issue((kt + 2) & 3, kt + 2);
            asm volatile("cp.async.wait_group 2;\n");
        } else if (kt + 1 < NIT) {
            asm volatile("cp.async.wait_group 1;\n");
        } else {
            asm volatile("cp.async.wait_group 0;\n");
        }
        __syncthreads();

        const __half* sA = smem + (kt & 3) * STG_ELEMS;
        const __half* sW = sA + 128 * SSTR;

        unsigned af[2][4];
        #pragma unroll
        for (int mi = 0; mi < 2; mi++)
            ldsm_x4_h(af[mi], sA + (warp_m + mi * 16 + a_row_l) * SSTR + a_col_l);
        #pragma unroll
        for (int nj = 0; nj < 4; nj++) {
            unsigned bh[4], bl[4];
            ldsm_x4_h(bh, sW + (warp_n + nj * 16 + b_row_l) * SSTR + b_col_l);
            ldsm_x4_h(bl, sW + 128 * SSTR + (warp_n + nj * 16 + b_row_l) * SSTR + b_col_l);
            #pragma unroll
            for (int mi = 0; mi < 2; mi++) {
                #pragma unroll
                for (int p = 0; p < 2; p++) {
                    float* c = acc[mi][nj * 2 + p];
                    MMA_F16(c, af[mi], bh[p * 2], bh[p * 2 + 1]);
                    MMA_F16(c, af[mi], bl[p * 2], bl[p * 2 + 1]);
                }
            }
        }
    }

    // epilogue: store partials (no atomics -> deterministic)
    float* gp = g_gp[z];
    const int g = lane >> 2, q2 = (lane & 3) * 2;
    #pragma unroll
    for (int mi = 0; mi < 2; mi++) {
        #pragma unroll
        for (int nt = 0; nt < 8; nt++) {
            int col = n0 + warp_n + nt * 8 + q2;
            int r0 = warp_m + mi * 16 + g;
            if (r0 < NB)
                *reinterpret_cast<float2*>(&gp[(size_t)r0 * NG + col]) =
                    make_float2(acc[mi][nt][0], acc[mi][nt][1]);
            int r1 = r0 + 8;
            if (r1 < NB)
                *reinterpret_cast<float2*>(&gp[(size_t)r1 * NG + col]) =
                    make_float2(acc[mi][nt][2], acc[mi][nt][3]);
        }
    }
}

// final LSTM (t = NT-1): writes out_hdd only
__global__ void k_last(const float* __restrict__ b_ih, const float* __restrict__ b_hh,
                       float* __restrict__ out_hdd) {
    int idx = blockIdx.x * 256 + threadIdx.x; // B*H
    int b = idx / NH, j = idx % NH;
    float gi = b_ih[j] + b_hh[j];
    float gf = b_ih[NH + j] + b_hh[NH + j];
    float gg = b_ih[2 * NH + j] + b_hh[2 * NH + j];
    float go = b_ih[3 * NH + j] + b_hh[3 * NH + j];
    #pragma unroll
    for (int z = 0; z < KSPLIT; z++) {
        const float* gp = g_gp[z] + (size_t)b * NG;
        gi += gp[j];
        gf += gp[NH + j];
        gg += gp[2 * NH + j];
        go += gp[3 * NH + j];
    }
    float c = sigmoidf_(gf) * g_c[idx] + sigmoidf_(gi) * tanhf(gg);
    float h = sigmoidf_(go) * tanhf(c);
    out_hdd[(size_t)(b * NT + (NT - 1)) * NH + j] = h;
}

// ---------------- host launcher ----------------
extern "C" void kernel_launch(void* const* d_in, const int* in_sizes, int n_in,
                              void* d_out, int out_size) {
    const float* feature = (const float*)d_in[0];
    const float* Wh_w = (const float*)d_in[1];
    const float* Wh_b = (const float*)d_in[2];
    const float* Wc_w = (const float*)d_in[3];
    const float* Wc_b = (const float*)d_in[4];
    const float* Wxa = (const float*)d_in[5];
    const float* Wha = (const float*)d_in[6];
    const float* wa = (const float*)d_in[7];
    const float* Wb = (const float*)d_in[8];
    const float* bb = (const float*)d_in[9];
    const float* W_ih = (const float*)d_in[10];
    const float* W_hh = (const float*)d_in[11];
    const float* b_ih = (const float*)d_in[12];
    const float* b_hh = (const float*)d_in[13];

    float* out = (float*)d_out;
    float* out_vis = out;
    float* out_hdd = out_vis + (size_t)NB * NT * NR;
    float* out_alp = out_hdd + (size_t)NB * NT * NH;
    float* out_bet = out_alp + (size_t)NB * NT * NL;

    static int attr_done = 0;
    if (!attr_done) {
        cudaFuncSetAttribute(k_mma, cudaFuncAttributeMaxDynamicSharedMemorySize, SMEM_BYTES);
        cudaFuncSetAttribute(k_xa2, cudaFuncAttributeMaxDynamicSharedMemorySize, XA_SMEM);
        attr_done = 1;
    }

    // t-independent precompute
    k_f0<<<NB, ND>>>(feature);
    k_h0c0<<<dim3(NB, NH / 128), 128>>>(Wh_w, Wh_b, Wc_w, Wc_b);
    k_wsplit<<<(int)(((size_t)NG * NK) / 256), 256>>>(W_ih, W_hh);
    k_wxat<<<ND, NA>>>(Wxa);
    k_xa2<<<(NB * NT * NL) / 128, 512, XA_SMEM>>>(feature);

    for (int t = 0; t < NT; t++) {
        k_step<<<NB, 1024>>>(Wha, Wb, bb, wa, b_ih, b_hh, feature,
                             out_vis, out_alp, out_bet, out_hdd, t);
        k_mma<<<dim3(NG / 128, KSPLIT), 256, SMEM_BYTES>>>();
    }
    k_last<<<(NB * NH) / 256, 256>>>(b_ih, b_hh, out_hdd);
}

// round 16
// speedup vs baseline: 1.5154x; 1.5154x over previous
#include <cuda_runtime.h>
#include <cuda_bf16.h>
#include <cuda_fp16.h>
#include <math.h>
#include <stdint.h>

// Problem dims
constexpr int NB = 120;
constexpr int NT = 20;
constexpr int NL = 144;
constexpr int ND = 64;
constexpr int NH = 1024;
constexpr int NA = 256;
constexpr int NR = NL * ND;     // 9216
constexpr int NG = 4 * NH;      // 4096
constexpr int NK = NR + NH;     // 10240 (concat v|h)

// Recurrent GEMM config (fp16 single-pass)
constexpr int KSPLIT = 8;
constexpr int KPER = NK / KSPLIT;   // 1280
constexpr int BK = 32;
constexpr int NIT = KPER / BK;      // 40
constexpr int SSTR = 40;            // padded smem row stride (fp16); 80B*r mod 128 is a permutation
constexpr int STG_ELEMS = 2 * (128 * SSTR);      // A + W = 10240 els
constexpr int NSTG = 4;
constexpr int SMEM_BYTES = NSTG * STG_ELEMS * 2; // 81920 B

// XA GEMM config (unchanged bf16 3-pass)
constexpr int XA_SSTR = 72;
constexpr int XA_SMEM = (2 * 128 * XA_SSTR + 2 * 256 * XA_SSTR) * 2; // 110592 B

// -------- scratch (device globals; no runtime allocation) --------
__device__ float g_XA[(size_t)NB * NT * NL * NA]; // 354 MB: feature @ Wxa
__device__ float g_h0[NB * NH];
__device__ float g_c[NB * NH];
__device__ float g_f0[NB * ND];
__device__ float g_gp[KSPLIT][NB * NG];   // per-K-split GEMM partials
// fp16 operands for recurrent GEMM (.bss zero-init keeps pad rows zero)
__device__ __align__(16) __half g_Af[128 * NK];           // A fp16
__device__ __align__(16) __half g_W16[(size_t)NG * NK];   // W fp16
// bf16 hi/lo for XA prologue
__device__ __align__(16) __nv_bfloat16 g_WxaThi[NA * ND]; // Wxa^T [256][64]
__device__ __align__(16) __nv_bfloat16 g_WxaTlo[NA * ND];

__device__ __forceinline__ float sigmoidf_(float x) {
    return 1.f / (1.f + expf(-x));
}

__device__ __forceinline__ void split_bf16(float x, __nv_bfloat16& hi, __nv_bfloat16& lo) {
    hi = __float2bfloat16(x);
    lo = __float2bfloat16(x - __bfloat162float(hi));
}

__device__ __forceinline__ void cp_async16(void* smem_dst, const void* gmem_src) {
    unsigned sa = (unsigned)__cvta_generic_to_shared(smem_dst);
    asm volatile("cp.async.cg.shared.global [%0], [%1], 16;\n" :: "r"(sa), "l"(gmem_src));
}

__device__ __forceinline__ void ldsm_x4_b(unsigned* r, const __nv_bfloat16* p) {
    unsigned sa = (unsigned)__cvta_generic_to_shared(p);
    asm volatile("ldmatrix.sync.aligned.m8n8.x4.shared.b16 {%0,%1,%2,%3}, [%4];"
                 : "=r"(r[0]), "=r"(r[1]), "=r"(r[2]), "=r"(r[3]) : "r"(sa));
}

__device__ __forceinline__ void ldsm_x4_h(unsigned* r, const __half* p) {
    unsigned sa = (unsigned)__cvta_generic_to_shared(p);
    asm volatile("ldmatrix.sync.aligned.m8n8.x4.shared.b16 {%0,%1,%2,%3}, [%4];"
                 : "=r"(r[0]), "=r"(r[1]), "=r"(r[2]), "=r"(r[3]) : "r"(sa));
}

#define MMA_BF16(C, AV, B0, B1) \
    asm volatile( \
        "mma.sync.aligned.m16n8k16.row.col.f32.bf16.bf16.f32 " \
        "{%0,%1,%2,%3}, {%4,%5,%6,%7}, {%8,%9}, {%0,%1,%2,%3};\n" \
        : "+f"((C)[0]), "+f"((C)[1]), "+f"((C)[2]), "+f"((C)[3]) \
        : "r"((AV)[0]), "r"((AV)[1]), "r"((AV)[2]), "r"((AV)[3]), \
          "r"(B0), "r"(B1))

#define MMA_F16(C, AV, B0, B1) \
    asm volatile( \
        "mma.sync.aligned.m16n8k16.row.col.f32.f16.f16.f32 " \
        "{%0,%1,%2,%3}, {%4,%5,%6,%7}, {%8,%9}, {%0,%1,%2,%3};\n" \
        : "+f"((C)[0]), "+f"((C)[1]), "+f"((C)[2]), "+f"((C)[3]) \
        : "r"((AV)[0]), "r"((AV)[1]), "r"((AV)[2]), "r"((AV)[3]), \
          "r"(B0), "r"(B1))

// ---------------- init: f0 = mean_l feature[b*T+0, l, :] ----------------
__global__ void k_f0(const float* __restrict__ feat) {
    int b = blockIdx.x, d = threadIdx.x; // 64 threads
    const float* p = feat + (size_t)b * NT * NL * ND;
    float s = 0.f;
    for (int l = 0; l < NL; l++) s += p[l * ND + d];
    g_f0[b * ND + d] = s * (1.f / NL);
}

// h0 = tanh(f0 @ Wh_w^T + Wh_b), c0 = tanh(f0 @ Wc_w^T + Wc_b)
__global__ void k_h0c0(const float* __restrict__ Wh_w, const float* __restrict__ Wh_b,
                       const float* __restrict__ Wc_w, const float* __restrict__ Wc_b) {
    __shared__ float fs[ND];
    int b = blockIdx.x;
    int j = blockIdx.y * 128 + threadIdx.x;
    if (threadIdx.x < ND) fs[threadIdx.x] = g_f0[b * ND + threadIdx.x];
    __syncthreads();
    float sh = Wh_b[j], sc = Wc_b[j];
    #pragma unroll 8
    for (int d = 0; d < ND; d++) {
        float x = fs[d];
        sh += x * Wh_w[j * ND + d];
        sc += x * Wc_w[j * ND + d];
    }
    float h = tanhf(sh);
    g_h0[b * NH + j] = h;
    g_c[b * NH + j] = tanhf(sc);
    g_Af[b * NK + NR + j] = __float2half_rn(h);
}

// convert W = [W_ih | W_hh] to fp16   [NG][NK]
__global__ void k_wsplit(const float* __restrict__ W_ih, const float* __restrict__ W_hh) {
    size_t idx = (size_t)blockIdx.x * 256 + threadIdx.x; // NG*NK exactly
    int n = (int)(idx / NK), k = (int)(idx % NK);
    float x = (k < NR) ? W_ih[(size_t)n * NR + k] : W_hh[(size_t)n * NH + (k - NR)];
    g_W16[idx] = __float2half_rn(x);
}

// transpose + split Wxa [64][256] -> WxaT [256][64]
__global__ void k_wxat(const float* __restrict__ Wxa) {
    int d = blockIdx.x, a = threadIdx.x; // 64 blocks x 256 threads
    __nv_bfloat16 hi, lo;
    split_bf16(Wxa[d * NA + a], hi, lo);
    g_WxaThi[a * ND + d] = hi;
    g_WxaTlo[a * ND + d] = lo;
}

// ---------------- XA = feature @ Wxa via tensor cores (bf16 3-pass HMMA) ----------------
__global__ void __launch_bounds__(512) k_xa2(const float* __restrict__ feat) {
    extern __shared__ __nv_bfloat16 xsm[];
    __nv_bfloat16* sA = xsm;                       // 2 arr x 128 x XA_SSTR
    __nv_bfloat16* sW = xsm + 2 * 128 * XA_SSTR;   // 2 arr x 256 x XA_SSTR

    const int tid = threadIdx.x;
    const int wid = tid >> 5, lane = tid & 31;
    const int m0 = blockIdx.x * 128;

    #pragma unroll
    for (int q = 0; q < 8; q++) {
        int c = tid + q * 512;
        int kc = c & 7, row = (c >> 3) & 255, arr = c >> 11;
        const __nv_bfloat16* src = (arr ? g_WxaTlo : g_WxaThi) + row * ND + kc * 8;
        cp_async16(sW + arr * (256 * XA_SSTR) + row * XA_SSTR + kc * 8, src);
    }
    asm volatile("cp.async.commit_group;\n");

    #pragma unroll
    for (int q = 0; q < 4; q++) {
        int i = tid + q * 512;
        int row = i >> 4, c4 = (i & 15) * 4;
        float4 f = *reinterpret_cast<const float4*>(feat + (size_t)(m0 + row) * ND + c4);
        __nv_bfloat16 h0, l0, h1, l1, h2, l2, h3, l3;
        split_bf16(f.x, h0, l0); split_bf16(f.y, h1, l1);
        split_bf16(f.z, h2, l2); split_bf16(f.w, h3, l3);
        __nv_bfloat162* ph = reinterpret_cast<__nv_bfloat162*>(sA + row * XA_SSTR + c4);
        __nv_bfloat162* pl = reinterpret_cast<__nv_bfloat162*>(sA + 128 * XA_SSTR + row * XA_SSTR + c4);
        ph[0] = __nv_bfloat162(h0, h1); ph[1] = __nv_bfloat162(h2, h3);
        pl[0] = __nv_bfloat162(l0, l1); pl[1] = __nv_bfloat162(l2, l3);
    }
    asm volatile("cp.async.wait_group 0;\n");
    __syncthreads();

    const int warp_m = (wid & 3) * 32;
    const int warp_n = (wid >> 2) * 64;
    const int a_row_l = lane & 15;
    const int a_col_l = (lane >> 4) * 8;
    const int b_row_l = (lane & 7) + ((lane >> 4) << 3);
    const int b_col_l = ((lane >> 3) & 1) * 8;

    float acc[2][8][4];
    #pragma unroll
    for (int mi = 0; mi < 2; mi++)
        #pragma unroll
        for (int nt = 0; nt < 8; nt++)
            #pragma unroll
            for (int c = 0; c < 4; c++) acc[mi][nt][c] = 0.f;

    #pragma unroll
    for (int ks = 0; ks < 4; ks++) {
        unsigned af[2][2][4];
        #pragma unroll
        for (int arr = 0; arr < 2; arr++)
            #pragma unroll
            for (int mi = 0; mi < 2; mi++)
                ldsm_x4_b(af[arr][mi],
                          sA + arr * (128 * XA_SSTR) +
                          (warp_m + mi * 16 + a_row_l) * XA_SSTR + ks * 16 + a_col_l);
        #pragma unroll
        for (int nj = 0; nj < 4; nj++) {
            unsigned bh[4], bl[4];
            ldsm_x4_b(bh, sW + (warp_n + nj * 16 + b_row_l) * XA_SSTR + ks * 16 + b_col_l);
            ldsm_x4_b(bl, sW + 256 * XA_SSTR + (warp_n + nj * 16 + b_row_l) * XA_SSTR + ks * 16 + b_col_l);
            #pragma unroll
            for (int mi = 0; mi < 2; mi++) {
                #pragma unroll
                for (int p = 0; p < 2; p++) {
                    float* c = acc[mi][nj * 2 + p];
                    MMA_BF16(c, af[0][mi], bh[p * 2], bh[p * 2 + 1]);
                    MMA_BF16(c, af[0][mi], bl[p * 2], bl[p * 2 + 1]);
                    MMA_BF16(c, af[1][mi], bh[p * 2], bh[p * 2 + 1]);
                }
            }
        }
    }

    const int g = lane >> 2, q2 = (lane & 3) * 2;
    #pragma unroll
    for (int mi = 0; mi < 2; mi++) {
        #pragma unroll
        for (int nt = 0; nt < 8; nt++) {
            int col = warp_n + nt * 8 + q2;
            int r0 = warp_m + mi * 16 + g;
            *reinterpret_cast<float2*>(&g_XA[(size_t)(m0 + r0) * NA + col]) =
                make_float2(acc[mi][nt][0], acc[mi][nt][1]);
            *reinterpret_cast<float2*>(&g_XA[(size_t)(m0 + r0 + 8) * NA + col]) =
                make_float2(acc[mi][nt][2], acc[mi][nt][3]);
        }
    }
}

// ---------------- fused per-step kernel: LSTM(t-1) + attention + v ----------------
__global__ void __launch_bounds__(1024) k_step(const float* __restrict__ Wha,
                                               const float* __restrict__ Wb,
                                               const float* __restrict__ bb,
                                               const float* __restrict__ wa,
                                               const float* __restrict__ b_ih,
                                               const float* __restrict__ b_hh,
                                               const float* __restrict__ feat,
                                               float* __restrict__ out_vis,
                                               float* __restrict__ out_alp,
                                               float* __restrict__ out_bet,
                                               float* __restrict__ out_hdd,
                                               int t) {
    __shared__ float hs[NH];
    __shared__ float pa[4][NA];
    __shared__ float pb[8][ND];
    __shared__ float ha_s[NA];
    __shared__ float wa_s[NA];
    __shared__ float e_s[NL];
    __shared__ float red[256];
    __shared__ float alpha_s[NL];
    __shared__ float beta_s[ND];
    const int b = blockIdx.x, tid = threadIdx.x;

    if (t > 0) {
        const int j = tid;
        float gi = b_ih[j] + b_hh[j];
        float gf = b_ih[NH + j] + b_hh[NH + j];
        float gg = b_ih[2 * NH + j] + b_hh[2 * NH + j];
        float go = b_ih[3 * NH + j] + b_hh[3 * NH + j];
        #pragma unroll
        for (int z = 0; z < KSPLIT; z++) {
            const float* gp = g_gp[z] + (size_t)b * NG;
            gi += gp[j];
            gf += gp[NH + j];
            gg += gp[2 * NH + j];
            go += gp[3 * NH + j];
        }
        float c = sigmoidf_(gf) * g_c[b * NH + j] + sigmoidf_(gi) * tanhf(gg);
        float h = sigmoidf_(go) * tanhf(c);
        g_c[b * NH + j] = c;
        hs[j] = h;
        out_hdd[(size_t)(b * NT + (t - 1)) * NH + j] = h;
        g_Af[b * NK + NR + j] = __float2half_rn(h);
    } else {
        hs[tid] = g_h0[b * NH + tid];
    }
    if (tid < NA) wa_s[tid] = wa[tid];
    __syncthreads();

    {
        int a = tid & 255, q = tid >> 8;
        int k0 = q * 256;
        float s = 0.f;
        #pragma unroll 16
        for (int k = 0; k < 256; k++) s += hs[k0 + k] * Wha[(size_t)(k0 + k) * NA + a];
        pa[q][a] = s;
    }
    if (tid < 512) {
        int d = tid & 63, q = tid >> 6;
        int k0 = q * 128;
        float s = 0.f;
        #pragma unroll 16
        for (int k = 0; k < 128; k++) s += hs[k0 + k] * Wb[(size_t)(k0 + k) * ND + d];
        pb[q][d] = s;
    }
    __syncthreads();
    if (tid < 256) {
        ha_s[tid] = pa[0][tid] + pa[1][tid] + pa[2][tid] + pa[3][tid];
    } else if (tid < 320) {
        int d = tid - 256;
        float tot = bb[d];
        #pragma unroll
        for (int i = 0; i < 8; i++) tot += pb[i][d];
        float bt = sigmoidf_(tot);
        beta_s[d] = bt;
        out_bet[(size_t)(b * NT + t) * ND + d] = bt;
    }
    __syncthreads();

    {
        const int w = tid >> 5, lane = tid & 31;
        const float* XAb = g_XA + (size_t)((b * NT + t) * NL) * NA;
        for (int l = w; l < NL; l += 32) {
            float s = 0.f;
            #pragma unroll
            for (int i = 0; i < 8; i++) {
                int a = lane + i * 32;
                s += tanhf(XAb[(size_t)l * NA + a] + ha_s[a]) * wa_s[a];
            }
            #pragma unroll
            for (int o = 16; o > 0; o >>= 1) s += __shfl_xor_sync(0xffffffffu, s, o);
            if (lane == 0) e_s[l] = s;
        }
    }
    __syncthreads();

    float v = -1e30f;
    if (tid < NL) v = e_s[tid];
    if (tid < 256) red[tid] = v;
    __syncthreads();
    for (int s2 = 128; s2 > 0; s2 >>= 1) {
        if (tid < s2) red[tid] = fmaxf(red[tid], red[tid + s2]);
        __syncthreads();
    }
    float mx = red[0];
    __syncthreads();
    float ex = (tid < NL) ? expf(v - mx) : 0.f;
    if (tid < 256) red[tid] = ex;
    __syncthreads();
    for (int s2 = 128; s2 > 0; s2 >>= 1) {
        if (tid < s2) red[tid] += red[tid + s2];
        __syncthreads();
    }
    float denom = red[0];
    if (tid < NL) {
        float al = ex / denom;
        alpha_s[tid] = al;
        out_alp[(size_t)(b * NT + t) * NL + tid] = al;
    }
    __syncthreads();

    {
        const float* fb = feat + (size_t)(b * NT + t) * NR;
        float* ob = out_vis + (size_t)(b * NT + t) * NR;
        __half* af = g_Af + (size_t)b * NK;
        #pragma unroll
        for (int q = 0; q < NR / 1024; q++) {
            int r = tid + q * 1024;
            int l = r >> 6, d = r & 63;
            float val = fb[r] * (1.f + alpha_s[l]) * beta_s[d];
            ob[r] = val;
            af[r] = __float2half_rn(val);
        }
    }
}

// ---------------- HMMA GEMM: gp[z] = A[128,Kz] @ W[4096,Kz]^T ----------------
// fp16 single-pass. BM=128, BN=128, BK=32, 8 warps, ldmatrix.x4,
// 4-stage cp.async, ONE sync per iter, 2 CTAs/SM.
__global__ void __launch_bounds__(256, 2) k_mma() {
    extern __shared__ __half smem[];

    const int tid = threadIdx.x;
    const int wid = tid >> 5, lane = tid & 31;
    const int warp_m = (wid & 3) * 32;
    const int warp_n = (wid >> 2) * 64;
    const int n0 = blockIdx.x * 128;
    const int z = blockIdx.y;
    const int kbase = z * KPER;

    // per iter: A 512 chunks + W 512 chunks of 16B; 4 per thread.
    auto issue = [&](int stage, int kt) {
        const int k0 = kbase + kt * BK;
        __half* sA = smem + stage * STG_ELEMS;
        __half* sW = sA + 128 * SSTR;
        #pragma unroll
        for (int q = 0; q < 2; q++) {
            int c = tid + q * 256;
            int kc = c & 3, row = c >> 2;
            const __half* srcA = g_Af + (size_t)row * NK + k0 + kc * 8;
            cp_async16(sA + row * SSTR + kc * 8, srcA);
            const __half* srcW = g_W16 + (size_t)(n0 + row) * NK + k0 + kc * 8;
            cp_async16(sW + row * SSTR + kc * 8, srcW);
        }
        asm volatile("cp.async.commit_group;\n");
    };

    float acc[2][8][4];
    #pragma unroll
    for (int mi = 0; mi < 2; mi++)
        #pragma unroll
        for (int nt = 0; nt < 8; nt++)
            #pragma unroll
            for (int c = 0; c < 4; c++) acc[mi][nt][c] = 0.f;

    issue(0, 0);
    issue(1, 1);

    const int a_row_l = lane & 15;
    const int a_col_l = (lane >> 4) * 8;
    const int b_row_l = (lane & 7) + ((lane >> 4) << 3);
    const int b_col_l = ((lane >> 3) & 1) * 8;

    for (int kt = 0; kt < NIT; kt++) {
        if (kt + 2 < NIT) {
            issue((kt + 2) & 3, kt + 2);
            asm volatile("cp.async.wait_group 2;\n");
        } else if (kt + 1 < NIT) {
            asm volatile("cp.async.wait_group 1;\n");
        } else {
            asm volatile("cp.async.wait_group 0;\n");
        }
        __syncthreads();

        const __half* sA = smem + (kt & 3) * STG_ELEMS;
        const __half* sW = sA + 128 * SSTR;

        #pragma unroll
        for (int ks = 0; ks < 2; ks++) {
            unsigned af[2][4];
            #pragma unroll
            for (int mi = 0; mi < 2; mi++)
                ldsm_x4_h(af[mi],
                          sA + (warp_m + mi * 16 + a_row_l) * SSTR + ks * 16 + a_col_l);
            #pragma unroll
            for (int nj = 0; nj < 4; nj++) {
                unsigned bh[4];
                ldsm_x4_h(bh, sW + (warp_n + nj * 16 + b_row_l) * SSTR + ks * 16 + b_col_l);
                #pragma unroll
                for (int mi = 0; mi < 2; mi++) {
                    #pragma unroll
                    for (int p = 0; p < 2; p++) {
                        float* c = acc[mi][nj * 2 + p];
                        MMA_F16(c, af[mi], bh[p * 2], bh[p * 2 + 1]);
                    }
                }
            }
        }
    }

    // epilogue: store partials (no atomics -> deterministic)
    float* gp = g_gp[z];
    const int g = lane >> 2, q2 = (lane & 3) * 2;
    #pragma unroll
    for (int mi = 0; mi < 2; mi++) {
        #pragma unroll
        for (int nt = 0; nt < 8; nt++) {
            int col = n0 + warp_n + nt * 8 + q2;
            int r0 = warp_m + mi * 16 + g;
            if (r0 < NB)
                *reinterpret_cast<float2*>(&gp[(size_t)r0 * NG + col]) =
                    make_float2(acc[mi][nt][0], acc[mi][nt][1]);
            int r1 = r0 + 8;
            if (r1 < NB)
                *reinterpret_cast<float2*>(&gp[(size_t)r1 * NG + col]) =
                    make_float2(acc[mi][nt][2], acc[mi][nt][3]);
        }
    }
}

// final LSTM (t = NT-1): writes out_hdd only
__global__ void k_last(const float* __restrict__ b_ih, const float* __restrict__ b_hh,
                       float* __restrict__ out_hdd) {
    int idx = blockIdx.x * 256 + threadIdx.x; // B*H
    int b = idx / NH, j = idx % NH;
    float gi = b_ih[j] + b_hh[j];
    float gf = b_ih[NH + j] + b_hh[NH + j];
    float gg = b_ih[2 * NH + j] + b_hh[2 * NH + j];
    float go = b_ih[3 * NH + j] + b_hh[3 * NH + j];
    #pragma unroll
    for (int z = 0; z < KSPLIT; z++) {
        const float* gp = g_gp[z] + (size_t)b * NG;
        gi += gp[j];
        gf += gp[NH + j];
        gg += gp[2 * NH + j];
        go += gp[3 * NH + j];
    }
    float c = sigmoidf_(gf) * g_c[idx] + sigmoidf_(gi) * tanhf(gg);
    float h = sigmoidf_(go) * tanhf(c);
    out_hdd[(size_t)(b * NT + (NT - 1)) * NH + j] = h;
}

// ---------------- host launcher ----------------
extern "C" void kernel_launch(void* const* d_in, const int* in_sizes, int n_in,
                              void* d_out, int out_size) {
    const float* feature = (const float*)d_in[0];
    const float* Wh_w = (const float*)d_in[1];
    const float* Wh_b = (const float*)d_in[2];
    const float* Wc_w = (const float*)d_in[3];
    const float* Wc_b = (const float*)d_in[4];
    const float* Wxa = (const float*)d_in[5];
    const float* Wha = (const float*)d_in[6];
    const float* wa = (const float*)d_in[7];
    const float* Wb = (const float*)d_in[8];
    const float* bb = (const float*)d_in[9];
    const float* W_ih = (const float*)d_in[10];
    const float* W_hh = (const float*)d_in[11];
    const float* b_ih = (const float*)d_in[12];
    const float* b_hh = (const float*)d_in[13];

    float* out = (float*)d_out;
    float* out_vis = out;
    float* out_hdd = out_vis + (size_t)NB * NT * NR;
    float* out_alp = out_hdd + (size_t)NB * NT * NH;
    float* out_bet = out_alp + (size_t)NB * NT * NL;

    static int attr_done = 0;
    if (!attr_done) {
        cudaFuncSetAttribute(k_mma, cudaFuncAttributeMaxDynamicSharedMemorySize, SMEM_BYTES);
        cudaFuncSetAttribute(k_xa2, cudaFuncAttributeMaxDynamicSharedMemorySize, XA_SMEM);
        attr_done = 1;
    }

    // t-independent precompute
    k_f0<<<NB, ND>>>(feature);
    k_h0c0<<<dim3(NB, NH / 128), 128>>>(Wh_w, Wh_b, Wc_w, Wc_b);
    k_wsplit<<<(int)(((size_t)NG * NK) / 256), 256>>>(W_ih, W_hh);
    k_wxat<<<ND, NA>>>(Wxa);
    k_xa2<<<(NB * NT * NL) / 128, 512, XA_SMEM>>>(feature);

    for (int t = 0; t < NT; t++) {
        k_step<<<NB, 1024>>>(Wha, Wb, bb, wa, b_ih, b_hh, feature,
                             out_vis, out_alp, out_bet, out_hdd, t);
        k_mma<<<dim3(NG / 128, KSPLIT), 256, SMEM_BYTES>>>();
    }
    k_last<<<(NB * NH) / 256, 256>>>(b_ih, b_hh, out_hdd);
}